// round 8
// baseline (speedup 1.0000x reference)
#include <cuda_runtime.h>

// Problem constants (fixed by the reference).
#define B_DIM   16384
#define T_DIM   512
#define HOR     32
#define NSTEP   (T_DIM + B_DIM - 1)   // 16895 scan steps
#define NPAD    16896                 // 132 * 128
#define NBLK    132                   // chunks of 128 steps (= queue depth M)

// Scratch (__device__ globals; zero-initialized at load).
__device__ float g_ts[NPAD];
__device__ float g_xnorm[NPAD];
__device__ float g_levels[NPAD];
__device__ float g_sseq[NPAD];
__device__ int   g_flag[NBLK];        // gather chunk ready
__device__ int   g_done;              // producers finished count
__device__ int   g_sflag[17];         // scan 8-chunk group ready (16 = all)
__device__ int   g_exit;              // exit counter for self-cleanup

__device__ __forceinline__ float frcp(float x) {
    float r;
    asm("rcp.approx.ftz.f32 %0, %1;" : "=f"(r) : "f"(x));
    return r;
}
__device__ __forceinline__ void spin_flag(const int* p) {
    const volatile int* vp = (const volatile int*)p;
    while (*vp == 0) { }
    __threadfence();                  // acquire
}
__device__ __forceinline__ void spin_done() {
    const volatile int* vp = (const volatile int*)&g_done;
    while (*vp < NBLK) { }
    __threadfence();
}

// One scan block = 128 steps. I becomes the TRUE level at this lane's last
// step (carry folded into lane0's input); l2,l1,l0 recovered backward.
// PIDX = prefetch index for chunk blk+3.
#define SCAN_BODY(BLK, PIDX)                                                   \
  {                                                                            \
    const int base = (BLK) * 128 + t0;                                         \
    const float4 yf = *reinterpret_cast<const float4*>(g_ts + (PIDX));         \
    const float t1raw = fmaf(k, c2, c3);                                       \
    const float t2e   = fmaf(k, c0, c1);                                       \
    const float t1    = (lane == 0) ? fmaf(k4, Tc, t1raw) : t1raw;             \
    float I = fmaf(k2, t2e, t1);                                               \
    float tsh;                                                                 \
    tsh = __shfl_up_sync(FULL, I, 1);  if (lane >= 1)  I = fmaf(K0,  tsh, I);  \
    tsh = __shfl_up_sync(FULL, I, 2);  if (lane >= 2)  I = fmaf(K1,  tsh, I);  \
    tsh = __shfl_up_sync(FULL, I, 4);  if (lane >= 4)  I = fmaf(K2c, tsh, I);  \
    tsh = __shfl_up_sync(FULL, I, 8);  if (lane >= 8)  I = fmaf(K3,  tsh, I);  \
    tsh = __shfl_up_sync(FULL, I, 16); if (lane >= 16) I = fmaf(K4,  tsh, I);  \
    const float l3 = I;                                                        \
    const float l2 = fmaf(rk, l3, ncrk3);                                      \
    const float l1 = fmaf(rk, l2, ncrk2);                                      \
    const float l0 = fmaf(rk, l1, ncrk1);                                      \
    const float d1 = fmaf(os1, l1, gy1);                                       \
    const float rd1 = frcp(d1);                                                \
    const float d0 = fmaf(os0, l0, gy0);                                       \
    const float rd0 = frcp(d0);                                                \
    const float d2 = fmaf(os2, l2, gy2);                                       \
    const float d3 = fmaf(os3, l3, gy3);                                       \
    const float rd2 = frcp(d2), rd3 = frcp(d3);                                \
    const float m0 = ayn0 * l0, m1 = ayn1 * l1;                                \
    const float m2 = ayn2 * l2, m3 = ayn3 * l3;                                \
    const float nc0 = m0 * rd0, nc1 = m1 * rd1;                                \
    const float nc2 = m2 * rd2, nc3 = m3 * rd3;                                \
    Tc = __shfl_sync(FULL, I, 31);                                             \
    const float rl0 = frcp(l0), rl1 = frcp(l1), rl2 = frcp(l2), rl3 = frcp(l3);\
    const float sn0 = d0 * rl0, sn1 = d1 * rl1, sn2 = d2 * rl2, sn3 = d3 * rl3;\
    const float xn0 = (y0 * rs0) * rl0;                                        \
    const float xn1 = (y1 * rs1) * rl1;                                        \
    const float xn2 = (y2 * rs2) * rl2;                                        \
    const float xn3 = (y3 * rs3) * rl3;                                        \
    *reinterpret_cast<float4*>(g_xnorm  + base) = make_float4(xn0, xn1, xn2, xn3); \
    *reinterpret_cast<float4*>(g_levels + base) = make_float4(l0, l1, l2, l3); \
    *reinterpret_cast<float4*>(g_sseq   + base) = make_float4(sn0, sn1, sn2, sn3); \
    rs0 = l0 * rd0; rs1 = l1 * rd1; rs2 = l2 * rd2; rs3 = l3 * rd3;            \
    os0 = omg * sn0; os1 = omg * sn1; os2 = omg * sn2; os3 = omg * sn3;        \
    c0 = nc0; c1 = nc1; c2 = nc2; c3 = nc3;                                    \
    ncrk1 = -(nc1 * rk); ncrk2 = -(nc2 * rk); ncrk3 = -(nc3 * rk);             \
    gy0 = g * yn0; gy1 = g * yn1; gy2 = g * yn2; gy3 = g * yn3;                \
    y0 = yn0; y1 = yn1; y2 = yn2; y3 = yn3;                                    \
    yn0 = ynn.x; yn1 = ynn.y; yn2 = ynn.z; yn3 = ynn.w;                        \
    ayn0 = a * yn0; ayn1 = a * yn1; ayn2 = a * yn2; ayn3 = a * yn3;            \
    ynn = yf;                                                                  \
  }

// ---------------------------------------------------------------------------
// Persistent fused kernel. Grid = 133 blocks x 256 threads (all resident).
//  block 0, warp 0 : scanner (Kogge-Stone blocked linear scan)
//  blocks 1..132   : gather chunk (blockIdx-1), publish flag, then OUT work
//                    pipelined behind the scanner via g_sflag groups.
// Last block to finish resets all flags (graph-replay clean).
// ---------------------------------------------------------------------------
__global__ void __launch_bounds__(256, 1)
fused_kernel(const float* __restrict__ x,
             const float* __restrict__ alpha, const float* __restrict__ gamma,
             const float* __restrict__ init_s, const float* __restrict__ level0,
             float* __restrict__ out) {
    const int bid = blockIdx.x;
    const int tid = threadIdx.x;

    if (bid != 0) {
        // ---- producer: gather one 128-element chunk of the effective series.
        const int j = bid - 1;
        if (tid < 128) {
            const int i = j * 128 + tid;
            float v;
            if (i < T_DIM)       v = __ldg(x + i);
            else if (i < NSTEP)  v = __ldg(x + (i - (T_DIM - 1)) * T_DIM + (T_DIM - 1));
            else                 v = 1.0f;
            g_ts[i] = v;
        }
        __threadfence();                  // each thread orders its own store
        __syncthreads();
        if (tid == 0) {
            g_flag[j] = 1;
            __threadfence();
            atomicAdd(&g_done, 1);
        }

        // ---- out worker: gate once on the scan group covering this block's
        //      data, then stream stores (overlaps the remaining scan).
        const int w = bid;                               // 1..132
        const int chunk_x = min(131, w + 3);             // x-part needs chunks <= w+3
        const int chunk_d = min(131, (125 * w + 510) >> 7);
        const int grp = max(chunk_x, chunk_d) >> 3;      // 8-chunk groups
        if (tid == 0) spin_flag(&g_sflag[grp]);
        __syncthreads();

        // x-part: rows b = 4*b4 + r, b4 in [32(w-1), 32w). Warp shares b4,
        // consecutive q -> coalesced loads (X4[b4+q]) and stores.
        const float4* __restrict__ X4 = reinterpret_cast<const float4*>(g_xnorm);
        const int b4base = 32 * (w - 1);
        if (b4base < 4096) {
            #pragma unroll 2
            for (int p = 0; p < 16; ++p) {
                const int b4 = b4base + 2 * p + (tid >> 7);
                if (b4 < 4096) {
                    const int q = tid & 127;
                    const int i4 = b4 + q;
                    const float4 A = X4[i4];
                    const float4 B = X4[i4 + 1];
                    const int rbase = b4 * 4 * T_DIM + q * 4;
                    *reinterpret_cast<float4*>(out + rbase)             = A;
                    *reinterpret_cast<float4*>(out + rbase + T_DIM)     = make_float4(A.y, A.z, A.w, B.x);
                    *reinterpret_cast<float4*>(out + rbase + 2 * T_DIM) = make_float4(A.z, A.w, B.x, B.y);
                    *reinterpret_cast<float4*>(out + rbase + 3 * T_DIM) = make_float4(A.w, B.x, B.y, B.z);
                }
            }
        }

        // d-part: denorm[b][h] = (levels[b+511], sseq[b+384+h]); b in
        // [125(w-1), min(16384, 125w)), 16 float4 (pairs of horizons) per b.
        const int bs = 125 * (w - 1);
        const int be = min(B_DIM, 125 * w);
        const int ntask = (be - bs) * 16;
        for (int tt = tid; tt < ntask; tt += 256) {
            const int b = bs + (tt >> 4);
            const int i = tt & 15;
            const float lvl = g_levels[b + (T_DIM - 1)];
            const float sa  = g_sseq[b + 384 + 2 * i];
            const float sb  = g_sseq[b + 385 + 2 * i];
            *reinterpret_cast<float4*>(out + B_DIM * T_DIM + b * (2 * HOR) + 4 * i) =
                make_float4(lvl, sa, lvl, sb);
        }

        // ---- exit protocol: last of the 133 blocks resets all flags.
        __syncthreads();
        if (tid == 0) {
            __threadfence();
            if (atomicAdd(&g_exit, 1) == NBLK) {
                for (int i = 0; i < NBLK; ++i) g_flag[i] = 0;
                for (int i = 0; i < 17; ++i) g_sflag[i] = 0;
                g_done = 0;
                g_exit = 0;
            }
        }
        return;
    }

    // ======================= scanner (block 0, warp 0) =======================
    if (tid >= 32) return;

    const unsigned FULL = 0xFFFFFFFFu;
    const int lane = tid;
    const int t0 = lane * 4;

    const float a   = alpha[0];
    const float g   = gamma[0];
    const float k   = 1.0f - a;
    const float omg = 1.0f - g;
    const float k2 = k * k, k4 = k2 * k2;
    const float rk = 1.0f / k;
    const float K0 = k4, K1 = K0 * K0, K2c = K1 * K1, K3 = K2c * K2c, K4 = K3 * K3;

    float Tc = level0[0];

    spin_flag(&g_flag[0]); spin_flag(&g_flag[1]); spin_flag(&g_flag[2]);
    float4 ynv = *reinterpret_cast<const float4*>(g_ts + 128 + t0);
    float4 ynn = *reinterpret_cast<const float4*>(g_ts + 256 + t0);
    float4 yv  = *reinterpret_cast<const float4*>(g_ts + t0);
    float y0 = yv.x,  y1 = yv.y,  y2 = yv.z,  y3 = yv.w;
    float yn0 = ynv.x, yn1 = ynv.y, yn2 = ynv.z, yn3 = ynv.w;

    float4 sv = *reinterpret_cast<const float4*>(init_s + t0);
    float rs0 = frcp(sv.x), rs1 = frcp(sv.y), rs2 = frcp(sv.z), rs3 = frcp(sv.w);
    float c0 = (a * y0) * rs0, c1 = (a * y1) * rs1;
    float c2 = (a * y2) * rs2, c3 = (a * y3) * rs3;
    float ncrk1 = -(c1 * rk), ncrk2 = -(c2 * rk), ncrk3 = -(c3 * rk);
    float gy0 = g * y0, gy1 = g * y1, gy2 = g * y2, gy3 = g * y3;
    float os0 = omg * sv.x, os1 = omg * sv.y, os2 = omg * sv.z, os3 = omg * sv.w;
    float ayn0 = a * yn0, ayn1 = a * yn1, ayn2 = a * yn2, ayn3 = a * yn3;

    // Phase 1: chunks 0..15, gather-flag guarded; publish groups 0,1.
    #pragma unroll 1
    for (int blk = 0; blk < 16; ++blk) {
        spin_flag(&g_flag[blk + 3]);
        SCAN_BODY(blk, blk * 128 + t0 + 384);
        if ((blk & 7) == 7) {
            __threadfence();
            if (lane == 0) g_sflag[blk >> 3] = 1;
        }
    }
    spin_done();   // all g_ts ready; steady-state loop is unguarded.

    // Phase 2: chunks 16..127 in groups of 8 — inner body branch-free.
    #pragma unroll 1
    for (int grp = 2; grp < 16; ++grp) {
        #pragma unroll 2
        for (int u = 0; u < 8; ++u) {
            const int blk = grp * 8 + u;
            SCAN_BODY(blk, blk * 128 + t0 + 384);
        }
        __threadfence();
        if (lane == 0) g_sflag[grp] = 1;
    }

    // Phase 3: tail chunks 128..131 (prefetch clamped), publish final group.
    #pragma unroll 1
    for (int blk = 128; blk < NBLK; ++blk) {
        SCAN_BODY(blk, (blk < 129) ? blk * 128 + t0 + 384 : t0);
    }
    __threadfence();
    if (lane == 0) g_sflag[16] = 1;

    // exit protocol (scanner is one of the 133 participants)
    if (lane == 0) {
        __threadfence();
        if (atomicAdd(&g_exit, 1) == NBLK) {
            for (int i = 0; i < NBLK; ++i) g_flag[i] = 0;
            for (int i = 0; i < 17; ++i) g_sflag[i] = 0;
            g_done = 0;
            g_exit = 0;
        }
    }
}

// ---------------------------------------------------------------------------
// Launch. Inputs (metadata order): x, alpha, gamma, init_seasonality, level.
// ---------------------------------------------------------------------------
extern "C" void kernel_launch(void* const* d_in, const int* in_sizes, int n_in,
                              void* d_out, int out_size) {
    const float* x      = (const float*)d_in[0];
    const float* alpha  = (const float*)d_in[1];
    const float* gamma  = (const float*)d_in[2];
    const float* init_s = (const float*)d_in[3];
    const float* level  = (const float*)d_in[4];
    float* out = (float*)d_out;

    fused_kernel<<<NBLK + 1, 256>>>(x, alpha, gamma, init_s, level, out);
}

// round 10
// speedup vs baseline: 1.4738x; 1.4738x over previous
#include <cuda_runtime.h>

// Problem constants (fixed by the reference).
#define B_DIM   16384
#define T_DIM   512
#define HOR     32
#define NSTEP   (T_DIM + B_DIM - 1)   // 16895 scan steps
#define NPAD    16896                 // 132 * 128
#define NBLK    132                   // chunks of 128 steps (= queue depth M)

// Scratch (__device__ globals; zero-initialized).
__device__ float g_ts[NPAD];
__device__ float g_xnorm[NPAD];
__device__ float g_levels[NPAD];
__device__ float g_sseq[NPAD];

__device__ __forceinline__ float frcp(float x) {
    float r;
    asm("rcp.approx.ftz.f32 %0, %1;" : "=f"(r) : "f"(x));
    return r;
}

// ---------------------------------------------------------------------------
// Kernel 1: parallel gather of the effective series (R6-proven, 4.6us).
// ts[i] = x[0,i,0] (i<512) else x[i-511,511,0]; pad -> 1.
// Stream ordering guarantees completion before scan_kernel starts.
// ---------------------------------------------------------------------------
__global__ void prep_kernel(const float* __restrict__ x) {
    int i = blockIdx.x * blockDim.x + threadIdx.x;
    if (i < NPAD) {
        float v;
        if (i < T_DIM)       v = __ldg(x + i);
        else if (i < NSTEP)  v = __ldg(x + (i - (T_DIM - 1)) * T_DIM + (T_DIM - 1));
        else                 v = 1.0f;
        g_ts[i] = v;
    }
}

// Warp-0 scan body for one 128-step block. I becomes the TRUE level at this
// lane's last step (carry folded into lane0's input); l2,l1,l0 backward.
// NO xnorm work here (warp 1's job) -> minimal issue pressure.
#define SCAN_BODY(BLK, PIDX)                                                   \
  {                                                                            \
    const int base = (BLK) * 128 + t0;                                         \
    const float4 yf = *reinterpret_cast<const float4*>(g_ts + (PIDX));         \
    const float t1raw = fmaf(k, c2, c3);                                       \
    const float t2e   = fmaf(k, c0, c1);                                       \
    const float t1    = (lane == 0) ? fmaf(k4, Tc, t1raw) : t1raw;             \
    float I = fmaf(k2, t2e, t1);                                               \
    float tsh;                                                                 \
    tsh = __shfl_up_sync(FULL, I, 1);  if (lane >= 1)  I = fmaf(K0,  tsh, I);  \
    tsh = __shfl_up_sync(FULL, I, 2);  if (lane >= 2)  I = fmaf(K1,  tsh, I);  \
    tsh = __shfl_up_sync(FULL, I, 4);  if (lane >= 4)  I = fmaf(K2c, tsh, I);  \
    tsh = __shfl_up_sync(FULL, I, 8);  if (lane >= 8)  I = fmaf(K3,  tsh, I);  \
    tsh = __shfl_up_sync(FULL, I, 16); if (lane >= 16) I = fmaf(K4,  tsh, I);  \
    const float l3 = I;                                                        \
    const float l2 = fmaf(rk, l3, ncrk3);                                      \
    const float l1 = fmaf(rk, l2, ncrk2);                                      \
    const float l0 = fmaf(rk, l1, ncrk1);                                      \
    const float d1 = fmaf(os1, l1, gy1);                                       \
    const float rd1 = frcp(d1);                                                \
    const float d0 = fmaf(os0, l0, gy0);                                       \
    const float rd0 = frcp(d0);                                                \
    const float d2 = fmaf(os2, l2, gy2);                                       \
    const float d3 = fmaf(os3, l3, gy3);                                       \
    const float rd2 = frcp(d2), rd3 = frcp(d3);                                \
    const float nc0 = (ay0 * l0) * rd0, nc1 = (ay1 * l1) * rd1;                \
    const float nc2 = (ay2 * l2) * rd2, nc3 = (ay3 * l3) * rd3;                \
    Tc = __shfl_sync(FULL, I, 31);                                             \
    const float rl0 = frcp(l0), rl1 = frcp(l1), rl2 = frcp(l2), rl3 = frcp(l3);\
    const float sn0 = d0 * rl0, sn1 = d1 * rl1, sn2 = d2 * rl2, sn3 = d3 * rl3;\
    *reinterpret_cast<float4*>(g_levels + base) = make_float4(l0, l1, l2, l3); \
    *reinterpret_cast<float4*>(g_sseq   + base) = make_float4(sn0, sn1, sn2, sn3); \
    os0 = omg * sn0; os1 = omg * sn1; os2 = omg * sn2; os3 = omg * sn3;        \
    c0 = nc0; c1 = nc1; c2 = nc2; c3 = nc3;                                    \
    ncrk1 = -(nc1 * rk); ncrk2 = -(nc2 * rk); ncrk3 = -(nc3 * rk);             \
    gy0 = rga * ay0; gy1 = rga * ay1; gy2 = rga * ay2; gy3 = rga * ay3;        \
    ay0 = a * ynn.x; ay1 = a * ynn.y; ay2 = a * ynn.z; ay3 = a * ynn.w;        \
    ynn = yf;                                                                  \
  }

// ---------------------------------------------------------------------------
// Kernel 2: warp-specialized scan. 1 block x 64 threads.
//  warp 0 : serial Kogge-Stone blocked linear scan (critical path only);
//           publishes progress counter in SMEM every 4 blocks (+ at end).
//  warp 1 : lags behind; computes x_norm[t] = y_t * rcp(s_t * l_t) from
//           g_levels / g_sseq / g_ts and stores g_xnorm. Different SMSP
//           (wid%4), so its ~35 issue cyc/block don't tax warp 0's scheduler.
// ---------------------------------------------------------------------------
__global__ void __launch_bounds__(64, 1)
scan_kernel(const float* __restrict__ alpha, const float* __restrict__ gamma,
            const float* __restrict__ init_s, const float* __restrict__ level0) {
    __shared__ int s_cnt;              // # of scan blocks fully stored
    const unsigned FULL = 0xFFFFFFFFu;
    const int tid = threadIdx.x;
    const int lane = tid & 31;
    const int t0 = lane * 4;
    if (tid == 0) s_cnt = 0;
    __syncthreads();

    if (tid >= 32) {
        // ===================== warp 1: x_norm consumer =====================
        volatile int* vc = &s_cnt;
        #pragma unroll 1
        for (int blk = 0; blk < NBLK; ++blk) {
            while (*vc < blk + 1) { }
            __threadfence_block();     // acquire: order global reads below
            const int base = blk * 128 + t0;
            float4 y4 = *reinterpret_cast<const float4*>(g_ts + base);
            float4 l4 = *reinterpret_cast<const float4*>(g_levels + base);
            float4 s4 = (blk == 0)
                ? *reinterpret_cast<const float4*>(init_s + t0)
                : *reinterpret_cast<const float4*>(g_sseq + base - 128);
            float4 o;
            o.x = y4.x * frcp(s4.x * l4.x);
            o.y = y4.y * frcp(s4.y * l4.y);
            o.z = y4.z * frcp(s4.z * l4.z);
            o.w = y4.w * frcp(s4.w * l4.w);
            *reinterpret_cast<float4*>(g_xnorm + base) = o;
        }
        return;
    }

    // ========================= warp 0: scanner =========================
    const float a   = alpha[0];
    const float g   = gamma[0];
    const float k   = 1.0f - a;
    const float omg = 1.0f - g;
    const float k2 = k * k, k4 = k2 * k2;
    const float rk = 1.0f / k;
    const float rga = g / a;               // gy_{next} = (g/a) * ay
    const float K0 = k4, K1 = K0 * K0, K2c = K1 * K1, K3 = K2c * K2c, K4 = K3 * K3;

    float Tc = level0[0];

    float4 yv  = *reinterpret_cast<const float4*>(g_ts + t0);
    float4 ynv = *reinterpret_cast<const float4*>(g_ts + 128 + t0);
    float4 ynn = *reinterpret_cast<const float4*>(g_ts + 256 + t0);

    float4 sv = *reinterpret_cast<const float4*>(init_s + t0);
    float c0 = (a * yv.x) * frcp(sv.x), c1 = (a * yv.y) * frcp(sv.y);
    float c2 = (a * yv.z) * frcp(sv.z), c3 = (a * yv.w) * frcp(sv.w);
    float ncrk1 = -(c1 * rk), ncrk2 = -(c2 * rk), ncrk3 = -(c3 * rk);
    float gy0 = g * yv.x, gy1 = g * yv.y, gy2 = g * yv.z, gy3 = g * yv.w;
    float os0 = omg * sv.x, os1 = omg * sv.y, os2 = omg * sv.z, os3 = omg * sv.w;
    float ay0 = a * ynv.x, ay1 = a * ynv.y, ay2 = a * ynv.z, ay3 = a * ynv.w;

    // Main: blocks 0..127 in groups of 4 — branch-free inner body; publish
    // progress after each group so warp 1 can stream behind.
    #pragma unroll 1
    for (int grp = 0; grp < 32; ++grp) {
        #pragma unroll
        for (int u = 0; u < 4; ++u) {
            const int blk = grp * 4 + u;
            SCAN_BODY(blk, blk * 128 + t0 + 384);
        }
        __threadfence_block();
        if (lane == 0) *(volatile int*)&s_cnt = grp * 4 + 4;
    }

    // Tail 128..131 (prefetch clamped for 129+), final publish.
    SCAN_BODY(128, 128 * 128 + t0 + 384);
    SCAN_BODY(129, t0);
    SCAN_BODY(130, t0);
    SCAN_BODY(131, t0);
    __threadfence_block();
    if (lane == 0) *(volatile int*)&s_cnt = NBLK;
}

// ---------------------------------------------------------------------------
// Kernel 3: materialize outputs (R6-proven: 9.3us). One thread serves FOUR
// batch rows at one t-quad via two ALIGNED float4 loads; denorm in grid tail.
// ---------------------------------------------------------------------------
#define XTASKS ((B_DIM / 4) * (T_DIM / 4))     // 524288
#define DTASKS (B_DIM * (HOR / 2))             // 262144

__global__ void __launch_bounds__(256)
out_kernel(float* __restrict__ out) {
    const float4* __restrict__ X4 = reinterpret_cast<const float4*>(g_xnorm);
    int gid = blockIdx.x * blockDim.x + threadIdx.x;
    if (gid < XTASKS) {
        const int b4 = gid >> 7;
        const int q  = gid & 127;
        const int i4 = b4 + q;
        const float4 A = X4[i4];
        const float4 B = X4[i4 + 1];
        const int rbase = (b4 * 4) * T_DIM + q * 4;
        *reinterpret_cast<float4*>(out + rbase)             = A;
        *reinterpret_cast<float4*>(out + rbase + T_DIM)     = make_float4(A.y, A.z, A.w, B.x);
        *reinterpret_cast<float4*>(out + rbase + 2 * T_DIM) = make_float4(A.z, A.w, B.x, B.y);
        *reinterpret_cast<float4*>(out + rbase + 3 * T_DIM) = make_float4(A.w, B.x, B.y, B.z);
    } else {
        const int j = gid - XTASKS;
        if (j < DTASKS) {
            const int b = j >> 4;
            const int i = j & 15;
            const float lvl = g_levels[b + (T_DIM - 1)];
            const float sa  = g_sseq[b + 384 + 2 * i];
            const float sb  = g_sseq[b + 385 + 2 * i];
            *reinterpret_cast<float4*>(out + B_DIM * T_DIM + b * (2 * HOR) + 4 * i) =
                make_float4(lvl, sa, lvl, sb);
        }
    }
}

// ---------------------------------------------------------------------------
// Launch. Inputs (metadata order): x, alpha, gamma, init_seasonality, level.
// ---------------------------------------------------------------------------
extern "C" void kernel_launch(void* const* d_in, const int* in_sizes, int n_in,
                              void* d_out, int out_size) {
    const float* x      = (const float*)d_in[0];
    const float* alpha  = (const float*)d_in[1];
    const float* gamma  = (const float*)d_in[2];
    const float* init_s = (const float*)d_in[3];
    const float* level  = (const float*)d_in[4];
    float* out = (float*)d_out;

    prep_kernel<<<NBLK, 128>>>(x);
    scan_kernel<<<1, 64>>>(alpha, gamma, init_s, level);
    out_kernel<<<(XTASKS + DTASKS) / 256, 256>>>(out);
}